// round 17
// baseline (speedup 1.0000x reference)
#include <cuda_runtime.h>
#include <math.h>

#define NPIX 16384
#define QSCALE 0.35355339059327373f
#define QKS 132    // q|k slot stride in k2 smem
#define NBI 3600   // interior blocks
#define NBB 1984   // boundary blocks
#define K3_SMEM ((8192 + 64 * 65 + 64 * 257) * 4)

__device__ __align__(16) float g_y[NPIX * 256];   // per pixel: q*s | k | v | raw x
__device__ __align__(16) float g_osum[NPIX * 64];
__device__ __align__(16) float g_const[192];      // qkv row for masked/OOB slots
__device__ __align__(16) float g_qwT[64 * 192];   // [c][o]
__device__ __align__(16) float g_w1T[64 * 256];   // [c][u]
__device__ __align__(16) float g_w2T[256 * 64];   // [u][o]
__device__ __align__(16) float g_projT[64 * 64];  // [c][o]
__device__ __align__(16) float g_ebias[8 * 25 * 25];   // exp(bias) full (boundary)
__device__ __align__(16) float g_eb12[8 * 25 * 12];    // exp(bias)[h][r][c<12] (interior)
__device__ float g_cb[8 * 25];                    // sum_{c>=12} exp(bias)

__device__ __forceinline__ float wsum(float v) {
#pragma unroll
    for (int o = 16; o; o >>= 1) v += __shfl_xor_sync(0xffffffffu, v, o);
    return v;
}

// ---- packed fp32x2 helpers (FFMA2 path, sm_103a) ----
__device__ __forceinline__ unsigned long long pack2(float lo, float hi) {
    unsigned long long r;
    asm("mov.b64 %0, {%1, %2};" : "=l"(r) : "f"(lo), "f"(hi));
    return r;
}
__device__ __forceinline__ void fma2(unsigned long long& d, unsigned long long a, unsigned long long b) {
    asm("fma.rn.f32x2 %0, %1, %2, %0;" : "+l"(d) : "l"(a), "l"(b));
}
__device__ __forceinline__ float2 unpack2(unsigned long long v) {
    float lo, hi;
    asm("mov.b64 {%0, %1}, %2;" : "=f"(lo), "=f"(hi) : "l"(v));
    return make_float2(lo, hi);
}

// ---- prep: transposed weights + exp(bias) tables + const qkv row ----
__global__ void prep(const float* __restrict__ qw, const float* __restrict__ w1,
                     const float* __restrict__ w2, const float* __restrict__ pw,
                     const float* __restrict__ rpb,
                     const float* __restrict__ n1b, const float* __restrict__ qb) {
    for (int i = blockIdx.x * blockDim.x + threadIdx.x; i < 56944; i += gridDim.x * blockDim.x) {
        if (i < 12288) { int c = i / 192, o = i % 192; g_qwT[i] = qw[o * 64 + c]; }
        else if (i < 28672) { int j = i - 12288; int c = j / 256, u = j % 256; g_w1T[j] = w1[u * 64 + c]; }
        else if (i < 45056) { int j = i - 28672; int u = j / 64, c = j % 64; g_w2T[j] = w2[c * 256 + u]; }
        else if (i < 49152) { int j = i - 45056; int c = j / 64, o = j % 64; g_projT[j] = pw[o * 64 + c]; }
        else if (i < 54152) {
            int j = i - 49152; int h = j / 625, r = j % 625; int qi = r / 25, kj = r % 25;
            int idx = (qi / 5 - kj / 5 + 4) * 9 + (qi % 5 - kj % 5 + 4);
            g_ebias[j] = __expf(rpb[idx * 8 + h]);
        } else if (i < 56552) {
            int j = i - 54152; int h = j / 300, rem = j % 300; int r = rem / 12, c = rem % 12;
            int idx = (r / 5 - c / 5 + 4) * 9 + (r % 5 - c % 5 + 4);
            g_eb12[j] = __expf(rpb[idx * 8 + h]);
        } else if (i < 56752) {
            int j = i - 56552; int h = j / 25, r = j % 25;
            float s = 0.f;
            for (int c = 12; c < 25; c++) {
                int idx = (r / 5 - c / 5 + 4) * 9 + (r % 5 - c % 5 + 4);
                s += __expf(rpb[idx * 8 + h]);
            }
            g_cb[j] = s;
        } else {
            int o = i - 56752;   // const qkv row: LN(0) = n1b
            float a = qb[o];
            for (int c = 0; c < 64; c++) a += n1b[c] * qw[o * 64 + c];
            if (o < 64) a *= QSCALE;
            g_const[o] = a;
        }
    }
}

// ---- k1: LN1 + QKV, smem-staged weights + pixel-pair FFMA2. ----
__global__ __launch_bounds__(256) void k1(const float* __restrict__ x,
                                          const float* __restrict__ n1w,
                                          const float* __restrict__ n1b,
                                          const float* __restrict__ qb) {
    __shared__ float sWt[64 * 96];
    __shared__ float sA[64 * 65];
    int tid = threadIdx.x, lane = tid & 31, w = tid >> 5;
    int p0 = blockIdx.x * 64;

    float nw0 = n1w[lane], nw1 = n1w[lane + 32];
    float nb0 = n1b[lane], nb1 = n1b[lane + 32];
#pragma unroll
    for (int t = 0; t < 8; t++) {
        int pix = w * 8 + t;
        int wid = p0 + pix;
        int b = wid >> 12, hw = wid & 4095;
        const float* xb = x + (size_t)b * 262144 + hw;
        float x0 = __ldg(xb + (size_t)lane * 4096);
        float x1 = __ldg(xb + (size_t)(lane + 32) * 4096);
        float m  = wsum(x0 + x1) * (1.f / 64.f);
        float vv = wsum(x0 * x0 + x1 * x1) * (1.f / 64.f) - m * m;
        float rs = rsqrtf(vv + 1e-5f);
        sA[pix * 65 + lane]      = (x0 - m) * rs * nw0 + nb0;
        sA[pix * 65 + lane + 32] = (x1 - m) * rs * nw1 + nb1;
        float* yp = g_y + (size_t)wid * 256;
        yp[192 + lane] = x0; yp[224 + lane] = x1;
    }

#pragma unroll
    for (int oh = 0; oh < 2; oh++) {
        __syncthreads();
        {
            const float4* src = (const float4*)g_qwT;
            float4* dst = (float4*)sWt;
            for (int i = tid; i < 1536; i += 256) {
                int row = i / 24, c4 = i % 24;
                dst[i] = src[row * 48 + oh * 24 + c4];
            }
        }
        __syncthreads();
        unsigned long long accA[6], accB[6];
#pragma unroll
        for (int j = 0; j < 6; j++) { accA[j] = 0ull; accB[j] = 0ull; }
        const float* a0 = sA + lane * 65;
        const float* a1 = sA + (lane + 32) * 65;
        const float* wBase = sWt + w * 12;
#pragma unroll 4
        for (int k = 0; k < 64; k++) {
            unsigned long long aa0 = pack2(a0[k], a0[k]);
            unsigned long long aa1 = pack2(a1[k], a1[k]);
            const ulonglong2* wr = (const ulonglong2*)(wBase + k * 96);
            ulonglong2 w01 = wr[0];
            fma2(accA[0], w01.x, aa0); fma2(accB[0], w01.x, aa1);
            fma2(accA[1], w01.y, aa0); fma2(accB[1], w01.y, aa1);
            ulonglong2 w23 = wr[1];
            fma2(accA[2], w23.x, aa0); fma2(accB[2], w23.x, aa1);
            fma2(accA[3], w23.y, aa0); fma2(accB[3], w23.y, aa1);
            ulonglong2 w45 = wr[2];
            fma2(accA[4], w45.x, aa0); fma2(accB[4], w45.x, aa1);
            fma2(accA[5], w45.y, aa0); fma2(accB[5], w45.y, aa1);
        }
        float ov0[12], ov1[12];
#pragma unroll
        for (int j = 0; j < 6; j++) {
            int o = oh * 96 + w * 12 + 2 * j;
            float b0 = __ldg(qb + o), b1v = __ldg(qb + o + 1);
            float s0 = (o < 64) ? QSCALE : 1.f;
            float s1 = (o + 1 < 64) ? QSCALE : 1.f;
            float2 pA = unpack2(accA[j]);
            float2 pB = unpack2(accB[j]);
            ov0[2 * j]     = (pA.x + b0) * s0;
            ov0[2 * j + 1] = (pA.y + b1v) * s1;
            ov1[2 * j]     = (pB.x + b0) * s0;
            ov1[2 * j + 1] = (pB.y + b1v) * s1;
        }
        float* y0 = g_y + (size_t)(p0 + lane) * 256 + oh * 96 + w * 12;
        float* y1 = g_y + (size_t)(p0 + lane + 32) * 256 + oh * 96 + w * 12;
#pragma unroll
        for (int j4 = 0; j4 < 3; j4++) {
            *(float4*)(y0 + 4 * j4) = make_float4(ov0[4 * j4], ov0[4 * j4 + 1], ov0[4 * j4 + 2], ov0[4 * j4 + 3]);
            *(float4*)(y1 + 4 * j4) = make_float4(ov1[4 * j4], ov1[4 * j4 + 1], ov1[4 * j4 + 2], ov1[4 * j4 + 3]);
        }
    }
}

// ---- k2: merged window attention; q|k staged in smem, v|x read direct from gmem ----
__global__ __launch_bounds__(256, 4) void k2() {
    __shared__ float sQ[22 * QKS];       // per slot: q [0,64) | k [64,128)
    __shared__ float sED[4 * 1352];      // boundary overlays CB scratch at +1360
    __shared__ float sInv[4 * 200];
    __shared__ float sW[4 * 104];
    __shared__ int   sSlot[4][13];
    __shared__ int   sOffI[4][12];       // interior: per-pixel slot gmem offsets
    __shared__ int   sMap[25];
    __shared__ int   sOff[13];

    int tid = threadIdx.x;

    if (blockIdx.x < NBI) {
        // ================= interior path =================
        int idx = blockIdx.x;
        int b = idx / 900, rem = idx - b * 900;
        int h0 = 2 + rem / 15, w0 = 2 + (rem % 15) * 4;
        int base = (b << 12) + (h0 << 6) + w0;

        if (tid < 52) {
            int j = tid / 13, ls = tid - j * 13;
            int g = (ls < 5) ? ls + j : (ls < 10) ? 8 + (ls - 5) + j : (ls < 12) ? 16 + (ls - 10) + j : 21;
            sSlot[j][ls] = g;
        }
        if (tid >= 64 && tid < 112) {
            int t = tid - 64; int j = t / 12, s = t - j * 12;
            sOffI[j][s] = (base + j + (s / 5 - 2) * 64 + (s % 5 - 2)) * 256;
        }
        for (int i = tid; i < 22 * 32; i += 256) {
            int slot = i >> 5, jj = i & 31;
            float4 v;
            if (slot < 21) {
                int row, col;
                if (slot < 16) { row = slot >> 3; col = slot & 7; }
                else { row = 2; col = slot - 16; }
                int pp = base + (row - 2) * 64 + (col - 2);
                v = *(const float4*)(g_y + (size_t)pp * 256 + jj * 4);
            } else {
                v = *(const float4*)(g_const + jj * 4);
            }
            *(float4*)(sQ + slot * QKS + jj * 4) = v;
        }
        __syncthreads();

        // dots: broadcast-k scheme, half-warp group per (pix,h) pair
        {
            int w = tid >> 5, lane = tid & 31;
            int grp = lane >> 4, qi = lane & 15;
            bool act = qi < 13;
#pragma unroll
            for (int it = 0; it < 2; it++) {
                int pairidx = w * 4 + it * 2 + grp;
                int pix = pairidx >> 3, h = pairidx & 7;
                const int* sm = sSlot[pix];
                float4 qa = make_float4(0.f, 0.f, 0.f, 0.f), qd = qa;
                if (act) {
                    int gq = sm[qi];
                    qa = *(const float4*)(sQ + gq * QKS + h * 8);
                    qd = *(const float4*)(sQ + gq * QKS + h * 8 + 4);
                }
                float* ed = sED + pix * 1352 + h * 169 + qi * 13;
#pragma unroll
                for (int ki = 0; ki < 13; ki++) {
                    const float* kb = sQ + sm[ki] * QKS + 64 + h * 8;
                    float4 ka = *(const float4*)kb;
                    float4 kd = *(const float4*)(kb + 4);
                    float dot = qa.x * ka.x + qa.y * ka.y + qa.z * ka.z + qa.w * ka.w
                              + qd.x * kd.x + qd.y * kd.y + qd.z * kd.z + qd.w * kd.w;
                    if (act) ed[ki] = __expf(dot);
                }
            }
        }
        __syncthreads();

        // pass1
        for (int i = tid; i < 800; i += 256) {
            int pix = i / 200, t = i - pix * 200;
            int h = t / 25, r = t - h * 25;
            int qi = (r < 12) ? r : 12;
            const float* ed = sED + pix * 1352 + h * 169 + qi * 13;
            const float* eb = g_eb12 + h * 300 + r * 12;
            float4 e0 = __ldg((const float4*)eb);
            float4 e1 = __ldg((const float4*)(eb + 4));
            float4 e2 = __ldg((const float4*)(eb + 8));
            float den = __ldg(g_cb + h * 25 + r) * ed[12];
            den += e0.x * ed[0] + e0.y * ed[1] + e0.z * ed[2] + e0.w * ed[3];
            den += e1.x * ed[4] + e1.y * ed[5] + e1.z * ed[6] + e1.w * ed[7];
            den += e2.x * ed[8] + e2.y * ed[9] + e2.z * ed[10] + e2.w * ed[11];
            sInv[pix * 200 + t] = 1.f / den;
        }
        __syncthreads();

        // pass2
        for (int i = tid; i < 416; i += 256) {
            int pix = i / 104, t = i - pix * 104;
            int h = t / 13, c = t - h * 13;
            const float* ed = sED + pix * 1352 + h * 169;
            const float* iv = sInv + pix * 200 + h * 25;
            float w = 0.f, tt = 0.f;
            if (c < 12) {
                const float* eb = g_eb12 + h * 300 + c;
#pragma unroll
                for (int r = 0; r < 12; r++) w += iv[r] * ed[r * 13 + c] * __ldg(eb + r * 12);
#pragma unroll
                for (int r = 12; r < 25; r++) tt += iv[r] * __ldg(eb + r * 12);
                w += ed[156 + c] * tt;
            } else {
                const float* cb = g_cb + h * 25;
#pragma unroll
                for (int r = 0; r < 12; r++) w += iv[r] * ed[r * 13 + 12] * __ldg(cb + r);
#pragma unroll
                for (int r = 12; r < 25; r++) tt += iv[r] * __ldg(cb + r);
                w += ed[168] * tt;
            }
            sW[pix * 104 + t] = w;
        }
        __syncthreads();

        // pass3: v & x direct from gmem (each consumed once — no staging)
        {
            int pix = tid >> 6, ch = tid & 63, h = ch >> 3;
            const float* wv = sW + pix * 104 + h * 13;
            const int* off = sOffI[pix];
            float acc = wv[12] * g_const[128 + ch];
#pragma unroll
            for (int s = 0; s < 12; s++) {
                const float* yb = g_y + off[s];
                acc += wv[s] * __ldg(yb + 128 + ch) + __ldg(yb + 192 + ch);
            }
            g_osum[(size_t)(base + pix) * 64 + ch] = acc;
        }
    } else {
        // ================= boundary path =================
        float* sCB = sED + 1360;   // overlay (ED uses [0,1352))
        int t = blockIdx.x - NBI;
        int b = t / 496, u = t - b * 496;
        int h0, w0;
        if (u < 128)      { h0 = u >> 6; w0 = u & 63; }
        else if (u < 256) { int v = u - 128; h0 = 62 + (v >> 6); w0 = v & 63; }
        else              { int v = u - 256; h0 = 2 + v / 4; int c = v & 3; w0 = (c < 2) ? c : (60 + c); }
        int p = (b << 12) + (h0 << 6) + w0;

        if (tid < 25) {
            int ri = tid / 5 - 2, ci = tid % 5 - 2;
            int nh = h0 + ri, nw = w0 + ci;
            int ok = (tid < 12) && nh >= 0 && nh < 64 && nw >= 0 && nw < 64;
            sMap[tid] = ok ? tid : 12;
            if (tid < 13) sOff[tid] = -1;
            if (ok) sOff[tid] = ((b << 12) + (nh << 6) + nw) * 256;
        }
        __syncthreads();

        for (int i = tid; i < 13 * 32; i += 256) {
            int slot = i >> 5, jj = i & 31;
            int off = sOff[slot];
            float4 v;
            if (off >= 0) v = *(const float4*)(g_y + off + jj * 4);
            else          v = *(const float4*)(g_const + jj * 4);
            *(float4*)(sQ + slot * QKS + jj * 4) = v;
        }
        __syncthreads();

        if (tid < 104) {
            int h = tid / 13, qi = tid % 13;
            float4 qa = *(const float4*)(sQ + qi * QKS + h * 8);
            float4 qd = *(const float4*)(sQ + qi * QKS + h * 8 + 4);
            float* ed = sED + h * 169 + qi * 13;
#pragma unroll
            for (int ki = 0; ki < 13; ki++) {
                const float* kb = sQ + ki * QKS + 64 + h * 8;
                float4 ka = *(const float4*)kb;
                float4 kd = *(const float4*)(kb + 4);
                float dot = qa.x * ka.x + qa.y * ka.y + qa.z * ka.z + qa.w * ka.w
                          + qd.x * kd.x + qd.y * kd.y + qd.z * kd.z + qd.w * kd.w;
                ed[ki] = __expf(dot);
            }
        }
        __syncthreads();

        if (tid < 200) {
            int h = tid / 25, r = tid % 25;
            int qi = sMap[r];
            const float* eb = g_ebias + h * 625 + r * 25;
            const float* ed = sED + h * 169 + qi * 13;
            float den = 0.f, cb = 0.f;
#pragma unroll
            for (int col = 0; col < 25; col++) {
                int ki = sMap[col];
                float e = __ldg(eb + col);
                den += e * ed[ki];
                if (ki == 12) cb += e;
            }
            sInv[tid] = 1.f / den;
            sCB[tid] = cb;
        }
        __syncthreads();

        if (tid < 104) {
            int h = tid / 13, c = tid % 13;
            const float* ed = sED + h * 169;
            const float* iv = sInv + h * 25;
            float w = 0.f;
            if (c == 12) {
                const float* cb = sCB + h * 25;
#pragma unroll
                for (int r = 0; r < 25; r++) w += iv[r] * ed[sMap[r] * 13 + 12] * cb[r];
            } else if (sMap[c] == c) {
                const float* eb = g_ebias + h * 625 + c;
#pragma unroll
                for (int r = 0; r < 25; r++) w += iv[r] * ed[sMap[r] * 13 + c] * __ldg(eb + r * 25);
            }
            sW[tid] = w;
        }
        __syncthreads();

        if (tid < 64) {
            int ch = tid, h = ch >> 3;
            const float* w = sW + h * 13;
            float acc = w[12] * g_const[128 + ch];
#pragma unroll
            for (int s = 0; s < 12; s++) {
                int o = sOff[s];
                if (o >= 0) {
                    const float* yb = g_y + o;
                    acc += w[s] * __ldg(yb + 128 + ch) + __ldg(yb + 192 + ch);
                }
            }
            g_osum[(size_t)p * 64 + ch] = acc;
        }
    }
}

// ---- k3: fused LN2+MLP+proj, 64 pixels/block, pixel-pair packed FFMA2. ----
__global__ __launch_bounds__(256) void k3(const float* __restrict__ n2w, const float* __restrict__ n2b,
                                          const float* __restrict__ b1, const float* __restrict__ b2,
                                          const float* __restrict__ pb, float* __restrict__ out) {
    extern __shared__ float smem[];
    float* sWt = smem;
    float* sA  = smem + 8192;
    float* sH  = sA + 64 * 65;
    int tid = threadIdx.x, lane = tid & 31, w = tid >> 5;
    int p0 = blockIdx.x * 64;

#pragma unroll
    for (int t = 0; t < 8; t++) {
        int pix = w * 8 + t;
        const float* os = g_osum + (size_t)(p0 + pix) * 64;
        float x0 = os[lane], x1 = os[lane + 32];
        float m  = wsum(x0 + x1) * (1.f / 64.f);
        float vv = wsum(x0 * x0 + x1 * x1) * (1.f / 64.f) - m * m;
        float rs = rsqrtf(vv + 1e-5f);
        sA[pix * 65 + lane]      = (x0 - m) * rs * n2w[lane] + n2b[lane];
        sA[pix * 65 + lane + 32] = (x1 - m) * rs * n2w[lane + 32] + n2b[lane + 32];
    }

#pragma unroll
    for (int oh = 0; oh < 2; oh++) {
        __syncthreads();
        {
            const float4* src = (const float4*)g_w1T;
            float4* dst = (float4*)sWt;
            for (int i = tid; i < 2048; i += 256) {
                int row = i >> 5, c4 = i & 31;
                dst[i] = src[row * 64 + oh * 32 + c4];
            }
        }
        __syncthreads();
        unsigned long long acc2[16];
#pragma unroll
        for (int j = 0; j < 16; j++) acc2[j] = 0ull;
        const float* a0 = sA + lane * 65;
        const float* a1 = sA + (lane + 32) * 65;
        const float* wBase = sWt + w * 16;
#pragma unroll 4
        for (int k = 0; k < 64; k++) {
            unsigned long long aa = pack2(a0[k], a1[k]);
            const float4* wr = (const float4*)(wBase + k * 128);
#pragma unroll
            for (int j4 = 0; j4 < 4; j4++) {
                float4 wv = wr[j4];
                fma2(acc2[4 * j4 + 0], pack2(wv.x, wv.x), aa);
                fma2(acc2[4 * j4 + 1], pack2(wv.y, wv.y), aa);
                fma2(acc2[4 * j4 + 2], pack2(wv.z, wv.z), aa);
                fma2(acc2[4 * j4 + 3], pack2(wv.w, wv.w), aa);
            }
        }
        float* h0 = sH + lane * 257 + oh * 128 + w * 16;
        float* h1 = sH + (lane + 32) * 257 + oh * 128 + w * 16;
#pragma unroll
        for (int j = 0; j < 16; j++) {
            float bv = __ldg(b1 + oh * 128 + w * 16 + j);
            float2 p = unpack2(acc2[j]);
            float v0 = p.x + bv, v1 = p.y + bv;
            h0[j] = 0.5f * v0 * (1.f + erff(v0 * 0.70710678118f));
            h1[j] = 0.5f * v1 * (1.f + erff(v1 * 0.70710678118f));
        }
    }

    unsigned long long a2p[8];
#pragma unroll
    for (int j = 0; j < 8; j++) a2p[j] = 0ull;
#pragma unroll
    for (int kh = 0; kh < 2; kh++) {
        __syncthreads();
        {
            const float4* src = (const float4*)(g_w2T + kh * 128 * 64);
            float4* dst = (float4*)sWt;
            for (int i = tid; i < 2048; i += 256) dst[i] = src[i];
        }
        __syncthreads();
        const float* h0 = sH + lane * 257 + kh * 128;
        const float* h1 = sH + (lane + 32) * 257 + kh * 128;
        const float* wBase = sWt + w * 8;
#pragma unroll 4
        for (int k = 0; k < 128; k++) {
            unsigned long long hh = pack2(h0[k], h1[k]);
            const float4* wr = (const float4*)(wBase + k * 64);
            float4 w0 = wr[0], w1v = wr[1];
            fma2(a2p[0], pack2(w0.x, w0.x), hh);
            fma2(a2p[1], pack2(w0.y, w0.y), hh);
            fma2(a2p[2], pack2(w0.z, w0.z), hh);
            fma2(a2p[3], pack2(w0.w, w0.w), hh);
            fma2(a2p[4], pack2(w1v.x, w1v.x), hh);
            fma2(a2p[5], pack2(w1v.y, w1v.y), hh);
            fma2(a2p[6], pack2(w1v.z, w1v.z), hh);
            fma2(a2p[7], pack2(w1v.w, w1v.w), hh);
        }
    }
    __syncthreads();
    {
        const float* os0 = g_osum + (size_t)(p0 + lane) * 64 + w * 8;
        const float* os1 = g_osum + (size_t)(p0 + lane + 32) * 64 + w * 8;
        float* y0 = sA + lane * 65 + w * 8;
        float* y1 = sA + (lane + 32) * 65 + w * 8;
#pragma unroll
        for (int j = 0; j < 8; j++) {
            float bv = __ldg(b2 + w * 8 + j);
            float2 p = unpack2(a2p[j]);
            y0[j] = p.x + bv + __ldg(os0 + j);
            y1[j] = p.y + bv + __ldg(os1 + j);
        }
    }
    __syncthreads();

    {
        const float4* src = (const float4*)g_projT;
        float4* dst = (float4*)sWt;
        for (int i = tid; i < 1024; i += 256) dst[i] = src[i];
    }
    __syncthreads();

    unsigned long long a3p[8];
#pragma unroll
    for (int j = 0; j < 8; j++) a3p[j] = 0ull;
    {
        const float* y0 = sA + lane * 65;
        const float* y1 = sA + (lane + 32) * 65;
        const float* wBase = sWt + w * 8;
#pragma unroll 4
        for (int k = 0; k < 64; k++) {
            unsigned long long yy = pack2(y0[k], y1[k]);
            const float4* wr = (const float4*)(wBase + k * 64);
            float4 w0 = wr[0], w1v = wr[1];
            fma2(a3p[0], pack2(w0.x, w0.x), yy);
            fma2(a3p[1], pack2(w0.y, w0.y), yy);
            fma2(a3p[2], pack2(w0.z, w0.z), yy);
            fma2(a3p[3], pack2(w0.w, w0.w), yy);
            fma2(a3p[4], pack2(w1v.x, w1v.x), yy);
            fma2(a3p[5], pack2(w1v.y, w1v.y), yy);
            fma2(a3p[6], pack2(w1v.z, w1v.z), yy);
            fma2(a3p[7], pack2(w1v.w, w1v.w), yy);
        }
    }
    {
        int wid0 = p0 + lane, wid1 = p0 + lane + 32;
        float* ob0 = out + (size_t)(wid0 >> 12) * 262144 + (wid0 & 4095);
        float* ob1 = out + (size_t)(wid1 >> 12) * 262144 + (wid1 & 4095);
#pragma unroll
        for (int j = 0; j < 8; j++) {
            float pv = __ldg(pb + w * 8 + j);
            float2 p = unpack2(a3p[j]);
            ob0[(size_t)(w * 8 + j) * 4096] = p.x + pv;
            ob1[(size_t)(w * 8 + j) * 4096] = p.y + pv;
        }
    }
}

extern "C" void kernel_launch(void* const* d_in, const int* in_sizes, int n_in,
                              void* d_out, int out_size) {
    const float* x    = (const float*)d_in[0];
    const float* n1w  = (const float*)d_in[1];
    const float* n1b  = (const float*)d_in[2];
    const float* qw   = (const float*)d_in[3];
    const float* qb   = (const float*)d_in[4];
    const float* rpb  = (const float*)d_in[5];
    const float* n2w  = (const float*)d_in[6];
    const float* n2b  = (const float*)d_in[7];
    const float* w1   = (const float*)d_in[8];
    const float* b1   = (const float*)d_in[9];
    const float* w2   = (const float*)d_in[10];
    const float* b2   = (const float*)d_in[11];
    const float* pw   = (const float*)d_in[12];
    const float* pb   = (const float*)d_in[13];
    float* out = (float*)d_out;

    cudaFuncSetAttribute(k3, cudaFuncAttributeMaxDynamicSharedMemorySize, K3_SMEM);

    prep<<<64, 256>>>(qw, w1, w2, pw, rpb, n1b, qb);
    k1<<<256, 256>>>(x, n1w, n1b, qb);
    k2<<<NBI + NBB, 256>>>();
    k3<<<256, 256, K3_SMEM>>>(n2w, n2b, b1, b2, pb, out);
}